// round 5
// baseline (speedup 1.0000x reference)
#include <cuda_runtime.h>
#include <cuda_bf16.h>
#include <cstdint>
#include <math.h>

#define BB 128
#define TT 1024
#define HH 512
#define NCTA 41

// smem layout (bytes)
#define APLANE 18432                 // 128 rows * 144B
#define WPLANE 27648                 // 192 rows * 144B
#define OFF_A  0                     // 4 planes (2 buf x hi/lo) = 73728
#define OFF_W  73728                 // 4 planes = 110592
#define OFF_H  184320                // h state, up to 64*128*4 = 32768
#define OFF_MAP 217088               // 192 ints = 768
#define SMEM_BYTES 217856

// ------------------------- persistent device state ---------------------------
__device__ float g_ig0[65 * 1536];
__device__ __align__(16) __nv_bfloat16 g_hA[3][2][2][BB * HH];   // [lay][pp][hi/lo][b*512+g]
__device__ __align__(16) __nv_bfloat16 g_wbf[6][2][1536 * 512];  // [part][hi/lo]
__device__ unsigned g_bar_count, g_bar_gen;

// ------------------------------ helpers --------------------------------------
__device__ __forceinline__ float sigm(float x) { return 1.f / (1.f + __expf(-x)); }
__device__ __forceinline__ uint32_t smem_u32(const void* p) {
    uint32_t a;
    asm("{ .reg .u64 t; cvta.to.shared.u64 t, %1; cvt.u32.u64 %0, t; }" : "=r"(a) : "l"(p));
    return a;
}
__device__ __forceinline__ void ldsm4(uint32_t a, uint32_t& r0, uint32_t& r1,
                                      uint32_t& r2, uint32_t& r3) {
    asm volatile("ldmatrix.sync.aligned.m8n8.x4.shared.b16 {%0,%1,%2,%3}, [%4];"
                 : "=r"(r0), "=r"(r1), "=r"(r2), "=r"(r3) : "r"(a));
}
__device__ __forceinline__ void mma4(float* d, uint32_t a0, uint32_t a1, uint32_t a2,
                                     uint32_t a3, uint32_t b0, uint32_t b1) {
    asm volatile("mma.sync.aligned.m16n8k16.row.col.f32.bf16.bf16.f32 "
                 "{%0,%1,%2,%3},{%4,%5,%6,%7},{%8,%9},{%0,%1,%2,%3};"
                 : "+f"(d[0]), "+f"(d[1]), "+f"(d[2]), "+f"(d[3])
                 : "r"(a0), "r"(a1), "r"(a2), "r"(a3), "r"(b0), "r"(b1));
}
__device__ __forceinline__ void cp16(uint32_t dst, const void* src) {
    asm volatile("cp.async.cg.shared.global [%0], [%1], 16;" :: "r"(dst), "l"(src));
}
#define CP_COMMIT() asm volatile("cp.async.commit_group;" ::: "memory")
#define CP_WAIT1()  asm volatile("cp.async.wait_group 1;" ::: "memory")
#define CP_WAIT0()  asm volatile("cp.async.wait_group 0;" ::: "memory")

// ------------------------------ prep kernels ---------------------------------
__global__ void k_zero() {
    long i = (long)blockIdx.x * blockDim.x + threadIdx.x;
    __nv_bfloat16* pb = &g_hA[0][0][0][0];
    long nb = 3L * 2 * 2 * BB * HH;
    for (long j = i; j < nb; j += (long)gridDim.x * blockDim.x) pb[j] = __float2bfloat16(0.f);
    if (i == 0) { g_bar_count = 0u; g_bar_gen = 0u; }
}

__global__ void k_ig0(const float* __restrict__ emb, const float* __restrict__ w_ih,
                      const float* __restrict__ bias) {
    int idx = blockIdx.x * blockDim.x + threadIdx.x;
    if (idx >= 65 * 1536) return;
    int tok = idx / 1536, j = idx - tok * 1536;
    const float* e = emb + tok * HH;
    const float* w = w_ih + (long)j * HH;
    float acc = bias[j];
    #pragma unroll 8
    for (int k = 0; k < HH; ++k) acc += e[k] * w[k];
    g_ig0[idx] = acc;
}

__global__ void k_prepw(const float* __restrict__ w_ih, const float* __restrict__ w_hh,
                        const float* __restrict__ w_out) {
    long idx = (long)blockIdx.x * 256 + threadIdx.x;     // 6 * 1536 * 512
    if (idx >= 6L * 1536 * 512) return;
    int k = (int)(idx & 511);
    long r = idx >> 9;
    int row = (int)(r % 1536);
    int part = (int)(r / 1536);
    float v = 0.f;
    if (part == 0)      v = w_hh[(long)row * 512 + k];
    else if (part == 1) v = w_ih[(1536L + row) * 512 + k];
    else if (part == 2) v = w_hh[(1536L + row) * 512 + k];
    else if (part == 3) v = w_ih[(2L * 1536 + row) * 512 + k];
    else if (part == 4) v = w_hh[(2L * 1536 + row) * 512 + k];
    else if (row < 65)  v = w_out[(long)row * 512 + k];
    __nv_bfloat16 hi = __float2bfloat16(v);
    __nv_bfloat16 lo = __float2bfloat16(v - __bfloat162float(hi));
    g_wbf[part][0][(long)row * 512 + k] = hi;
    g_wbf[part][1][(long)row * 512 + k] = lo;
}

// ------------------------------ grid barrier ---------------------------------
__device__ __forceinline__ void grid_barrier(unsigned target) {
    __syncthreads();
    if (threadIdx.x == 0) {
        __threadfence();
        unsigned old = atomicAdd(&g_bar_count, 1u);
        if (old == NCTA - 1) {
            g_bar_count = 0u;
            __threadfence();
            atomicAdd(&g_bar_gen, 1u);
        } else {
            while (*((volatile unsigned*)&g_bar_gen) < target) { }
            __threadfence();
        }
    }
    __syncthreads();
}

// ------------------------------ GEMM core ------------------------------------
template <int NT>
__device__ __forceinline__ void consume_chunk(
    uint32_t ah, uint32_t al, uint32_t wh, uint32_t wl,
    float (&acc)[NT][4], int warp, int lane)
{
    const int lr = lane & 7, gq = lane >> 3;
    const uint32_t aoff = (uint32_t)((warp * 16 + lr + (gq & 1) * 8) * 144
                                     + ((gq >> 1) * 8) * 2);
    const uint32_t woff0 = (uint32_t)((lr + (gq & 1) * 8) * 144 + ((gq >> 1) * 8) * 2);
    #pragma unroll
    for (int ks = 0; ks < 4; ++ks) {
        uint32_t Ah0, Ah1, Ah2, Ah3, Al0, Al1, Al2, Al3;
        ldsm4(ah + aoff + ks * 32, Ah0, Ah1, Ah2, Ah3);
        ldsm4(al + aoff + ks * 32, Al0, Al1, Al2, Al3);
        #pragma unroll
        for (int p = 0; p < (NT + 1) / 2; ++p) {
            uint32_t wo = woff0 + (uint32_t)(p * 16 * 144) + ks * 32;
            uint32_t Bh0, Bh1, Bh2, Bh3, Bl0, Bl1, Bl2, Bl3;
            ldsm4(wh + wo, Bh0, Bh1, Bh2, Bh3);
            ldsm4(wl + wo, Bl0, Bl1, Bl2, Bl3);
            mma4(acc[2 * p], Ah0, Ah1, Ah2, Ah3, Bh0, Bh2);
            mma4(acc[2 * p], Ah0, Ah1, Ah2, Ah3, Bl0, Bl2);
            mma4(acc[2 * p], Al0, Al1, Al2, Al3, Bh0, Bh2);
            if (2 * p + 1 < NT) {
                mma4(acc[2 * p + 1], Ah0, Ah1, Ah2, Ah3, Bh1, Bh3);
                mma4(acc[2 * p + 1], Ah0, Ah1, Ah2, Ah3, Bl1, Bl3);
                mma4(acc[2 * p + 1], Al0, Al1, Al2, Al3, Bh1, Bh3);
            }
        }
    }
}

template <int NT, int NPH>
__device__ __forceinline__ void gemm_phases(
    const __nv_bfloat16* A0h, const __nv_bfloat16* A0l,
    const __nv_bfloat16* A1h, const __nv_bfloat16* A1l,
    const __nv_bfloat16* W0h, const __nv_bfloat16* W0l,
    const __nv_bfloat16* W1h, const __nv_bfloat16* W1l,
    int rowsStage, const int* __restrict__ rowmap, uint32_t sb,
    float (&acc)[NPH][NT][4], int tid)
{
    const int warp = tid >> 5, lane = tid & 31;
    const int wsegs = rowsStage * 8;

    auto stage = [&](int cg, int buf) {
        int ph = cg >> 3, kc = cg & 7;
        const __nv_bfloat16* ah  = (ph == 0) ? A0h : A1h;
        const __nv_bfloat16* alp = (ph == 0) ? A0l : A1l;
        const __nv_bfloat16* whp = (ph == 0) ? W0h : W1h;
        const __nv_bfloat16* wlp = (ph == 0) ? W0l : W1l;
        uint32_t aDst = sb + OFF_A + buf * 2 * APLANE;
        #pragma unroll
        for (int i = 0; i < 8; ++i) {
            int e = tid + i * 256;
            int p = e >> 10, rr = (e >> 3) & 127, u = e & 7;
            const __nv_bfloat16* s = (p ? alp : ah) + (long)rr * 512 + kc * 64 + u * 8;
            cp16(aDst + p * APLANE + rr * 144 + u * 16, s);
        }
        uint32_t wDst = sb + OFF_W + buf * 2 * WPLANE;
        for (int e = tid; e < 2 * wsegs; e += 256) {
            int p = (e >= wsegs) ? 1 : 0;
            int e2 = e - p * wsegs;
            int rr = e2 >> 3, u = e2 & 7;
            const __nv_bfloat16* s = (p ? wlp : whp) + (long)rowmap[rr] * 512 + kc * 64 + u * 8;
            cp16(wDst + p * WPLANE + rr * 144 + u * 16, s);
        }
        CP_COMMIT();
    };

    stage(0, 0);
    int cg = 0;
    #pragma unroll
    for (int ph = 0; ph < NPH; ++ph) {
        #pragma unroll 1
        for (int kc = 0; kc < 8; ++kc, ++cg) {
            int buf = cg & 1;
            if (cg + 1 < NPH * 8) { stage(cg + 1, buf ^ 1); CP_WAIT1(); }
            else CP_WAIT0();
            __syncthreads();
            uint32_t ab = sb + OFF_A + buf * 2 * APLANE;
            uint32_t wb = sb + OFF_W + buf * 2 * WPLANE;
            consume_chunk<NT>(ab, ab + APLANE, wb, wb + WPLANE, acc[ph], warp, lane);
            __syncthreads();
        }
    }
}

// slab write: h pair (adjacent g) -> hi/lo bf16 slabs
__device__ __forceinline__ void slab_store(__nv_bfloat16* sh, __nv_bfloat16* sl,
                                           int b, int g, float h0, float h1) {
    __nv_bfloat16 x0 = __float2bfloat16(h0), x1 = __float2bfloat16(h1);
    __nv_bfloat162 hv; hv.x = x0; hv.y = x1;
    __nv_bfloat162 lv;
    lv.x = __float2bfloat16(h0 - __bfloat162float(x0));
    lv.y = __float2bfloat16(h1 - __bfloat162float(x1));
    *(__nv_bfloat162*)(sh + (long)b * 512 + g) = hv;
    *(__nv_bfloat162*)(sl + (long)b * 512 + g) = lv;
}

// ------------------------------- main kernel ---------------------------------
__global__ void __launch_bounds__(256, 1) k_main(
    const int* __restrict__ x_seq,
    const float* __restrict__ bias, const float* __restrict__ b_n,
    const float* __restrict__ b_out, float* __restrict__ out)
{
    extern __shared__ unsigned char smem[];
    const uint32_t sb = smem_u32(smem);
    float* h_sm = (float*)(smem + OFF_H);
    int* rowmap = (int*)(smem + OFF_MAP);
    const int tid = threadIdx.x;
    const int warp = tid >> 5, lane = tid & 31;
    const int l3 = lane & 3, lr4 = lane >> 2;
    const int cta = blockIdx.x;

    // ---- role decode ----
    int role, lay = 0, n0 = 0, cols = 0, rowsStage;
    if (cta < 8)       { role = 0; lay = 0; n0 = cta * 64;        cols = 64; rowsStage = 192; }
    else if (cta < 24) { role = 1; lay = 1; n0 = (cta - 8) * 32;  cols = 32; rowsStage = 96; }
    else if (cta < 40) { role = 2; lay = 2; n0 = (cta - 24) * 32; cols = 32; rowsStage = 96; }
    else               { role = 3; lay = 3; n0 = 0;               cols = 0;  rowsStage = 80; }

    // weight part pointers per phase
    const __nv_bfloat16 *W0h, *W0l, *W1h, *W1l;
    if (role == 0)      { W0h = g_wbf[0][0]; W0l = g_wbf[0][1]; W1h = W0h; W1l = W0l; }
    else if (role == 1) { W0h = g_wbf[1][0]; W0l = g_wbf[1][1]; W1h = g_wbf[2][0]; W1l = g_wbf[2][1]; }
    else if (role == 2) { W0h = g_wbf[3][0]; W0l = g_wbf[3][1]; W1h = g_wbf[4][0]; W1l = g_wbf[4][1]; }
    else                { W0h = g_wbf[5][0]; W0l = g_wbf[5][1]; W1h = W0h; W1l = W0l; }

    // rowmap + h state init
    for (int r = tid; r < 192; r += 256) {
        int grow = 0;
        if (r < rowsStage) {
            if (role == 3) grow = r;                          // rows >= 65 are zero-padded
            else           grow = (r / cols) * 512 + n0 + (r % cols);
        }
        rowmap[r] = grow;
    }
    for (int e = tid; e < cols * 128; e += 256) h_sm[e] = 0.f;
    __syncthreads();

    const int b0 = 16 * warp + lr4;

    for (int s = 0; s < TT + 3; ++s) {
        const int rd = (s + 1) & 1, wr = s & 1;

        if (role == 0 && s < TT) {
            const int t = s;
            const __nv_bfloat16* Ah = g_hA[0][rd][0];
            const __nv_bfloat16* Al = g_hA[0][rd][1];
            float acc[1][24][4] = {};
            gemm_phases<24, 1>(Ah, Al, Ah, Al, W0h, W0l, W1h, W1l,
                               rowsStage, rowmap, sb, acc, tid);

            const int tok0 = __ldg(x_seq + (long)b0 * TT + t);
            const int tok1 = __ldg(x_seq + (long)(b0 + 8) * TT + t);
            __nv_bfloat16* sh = g_hA[0][wr][0];
            __nv_bfloat16* sl = g_hA[0][wr][1];
            #pragma unroll
            for (int jj = 0; jj < 8; ++jj) {
                int gl = 8 * jj + 2 * l3;
                int g = n0 + gl;
                float2 bn2 = *(const float2*)(b_n + g);
                #pragma unroll
                for (int bs = 0; bs < 2; ++bs) {
                    int b = b0 + 8 * bs;
                    const float* ig = g_ig0 + (long)(bs ? tok1 : tok0) * 1536;
                    float2 igr = *(const float2*)(ig + g);
                    float2 igz = *(const float2*)(ig + 512 + g);
                    float2 ign = *(const float2*)(ig + 1024 + g);
                    float h2[2];
                    #pragma unroll
                    for (int d = 0; d < 2; ++d) {
                        float rv = acc[0][jj][2 * bs + d];
                        float zv = acc[0][8 + jj][2 * bs + d];
                        float nv = acc[0][16 + jj][2 * bs + d];
                        float r = sigm((d ? igr.y : igr.x) + rv);
                        float z = sigm((d ? igz.y : igz.x) + zv);
                        float n = tanhf((d ? ign.y : ign.x)
                                        + r * (nv + (d ? bn2.y : bn2.x)));
                        float hp = h_sm[(gl + d) * 128 + b];
                        float h = n + z * (hp - n);
                        h_sm[(gl + d) * 128 + b] = h;
                        h2[d] = h;
                    }
                    slab_store(sh, sl, b, g, h2[0], h2[1]);
                }
            }
        } else if ((role == 1 || role == 2) && s >= lay && s <= TT + lay - 1) {
            const __nv_bfloat16* Axh = g_hA[lay - 1][rd][0];
            const __nv_bfloat16* Axl = g_hA[lay - 1][rd][1];
            const __nv_bfloat16* Ahh = g_hA[lay][rd][0];
            const __nv_bfloat16* Ahl = g_hA[lay][rd][1];
            float acc[2][12][4] = {};
            gemm_phases<12, 2>(Axh, Axl, Ahh, Ahl, W0h, W0l, W1h, W1l,
                               rowsStage, rowmap, sb, acc, tid);

            const float* bl = bias + (long)lay * 1536;
            const float* bnl = b_n + (long)lay * 512;
            __nv_bfloat16* sh = g_hA[lay][wr][0];
            __nv_bfloat16* sl = g_hA[lay][wr][1];
            #pragma unroll
            for (int jj = 0; jj < 4; ++jj) {
                int gl = 8 * jj + 2 * l3;
                int g = n0 + gl;
                float2 blr = *(const float2*)(bl + g);
                float2 blz = *(const float2*)(bl + 512 + g);
                float2 bln = *(const float2*)(bl + 1024 + g);
                float2 bn2 = *(const float2*)(bnl + g);
                #pragma unroll
                for (int bs = 0; bs < 2; ++bs) {
                    int b = b0 + 8 * bs;
                    float h2[2];
                    #pragma unroll
                    for (int d = 0; d < 2; ++d) {
                        float ir = acc[0][jj][2 * bs + d]     + (d ? blr.y : blr.x);
                        float iz = acc[0][4 + jj][2 * bs + d] + (d ? blz.y : blz.x);
                        float in_ = acc[0][8 + jj][2 * bs + d] + (d ? bln.y : bln.x);
                        float hr = acc[1][jj][2 * bs + d];
                        float hz = acc[1][4 + jj][2 * bs + d];
                        float hn = acc[1][8 + jj][2 * bs + d];
                        float r = sigm(ir + hr);
                        float z = sigm(iz + hz);
                        float n = tanhf(in_ + r * (hn + (d ? bn2.y : bn2.x)));
                        float hp = h_sm[(gl + d) * 128 + b];
                        float h = n + z * (hp - n);
                        h_sm[(gl + d) * 128 + b] = h;
                        h2[d] = h;
                    }
                    slab_store(sh, sl, b, g, h2[0], h2[1]);
                }
            }
        } else if (role == 3 && s >= 3) {
            const int t = s - 3;
            const __nv_bfloat16* Ah = g_hA[2][rd][0];
            const __nv_bfloat16* Al = g_hA[2][rd][1];
            float acc[1][9][4] = {};
            gemm_phases<9, 1>(Ah, Al, Ah, Al, W0h, W0l, W1h, W1l,
                               rowsStage, rowmap, sb, acc, tid);
            #pragma unroll
            for (int jj = 0; jj < 9; ++jj) {
                #pragma unroll
                for (int d = 0; d < 2; ++d) {
                    int v = 8 * jj + 2 * l3 + d;
                    if (v < 65) {
                        float bo = __ldg(b_out + v);
                        out[((long)b0 * TT + t) * 65 + v]       = acc[0][jj][d]     + bo;
                        out[((long)(b0 + 8) * TT + t) * 65 + v] = acc[0][jj][2 + d] + bo;
                    }
                }
            }
        }

        grid_barrier((unsigned)(s + 1));
    }
}

// --------------------------------- launch ------------------------------------
extern "C" void kernel_launch(void* const* d_in, const int* in_sizes, int n_in,
                              void* d_out, int out_size) {
    const int*   x_seq = (const int*)  d_in[0];
    const float* emb   = (const float*)d_in[1];
    const float* w_ih  = (const float*)d_in[2];
    const float* w_hh  = (const float*)d_in[3];
    const float* b     = (const float*)d_in[4];
    const float* b_n   = (const float*)d_in[5];
    const float* w_out = (const float*)d_in[6];
    const float* b_out = (const float*)d_in[7];
    float* out = (float*)d_out;

    cudaFuncSetAttribute(k_main, cudaFuncAttributeMaxDynamicSharedMemorySize, SMEM_BYTES);

    k_zero<<<512, 256>>>();
    k_ig0<<<(65 * 1536 + 255) / 256, 256>>>(emb, w_ih, b);
    k_prepw<<<(int)((6L * 1536 * 512 + 255) / 256), 256>>>(w_ih, w_hh, w_out);
    k_main<<<NCTA, 256, SMEM_BYTES>>>(x_seq, b, b_n, b_out, out);
}

// round 6
// speedup vs baseline: 1.1801x; 1.1801x over previous
#include <cuda_runtime.h>
#include <cuda_bf16.h>
#include <cstdint>
#include <math.h>

#define BB 128
#define TT 1024
#define HH 512
#define NCTA 122
#define NTHR 512
#define GT   (NCTA * NTHR)

// smem layout (bytes)
#define APLANE 18432                 // 128 rows * 144B (one 64k chunk, one plane)
#define OFF_A  0                     // 2 bufs x 2 planes = 73728
#define OFF_W  73728                 // persistent weights, max 133120
#define SMEM_BYTES 207360

// ------------------------- persistent device state ---------------------------
__device__ float g_ig0[65 * 1536];
__device__ float g_h_f32[3][2][BB][HH];
__device__ __align__(16) __nv_bfloat16 g_hA[3][2][2][BB * HH];   // [lay][pp][hi/lo][b*512+g]
__device__ __align__(16) __nv_bfloat16 g_wbf[6][2][1536 * 512];  // [part][hi/lo]
__device__ float g_gi[2][BB][1536];           // x-part gates, layers 1-2
__device__ float g_gh[3][BB][1536];           // h-part gates, layers 0-2
__device__ unsigned g_bar_count, g_bar_gen;

// ------------------------------ helpers --------------------------------------
__device__ __forceinline__ float sigm(float x) { return 1.f / (1.f + __expf(-x)); }
__device__ __forceinline__ uint32_t smem_u32(const void* p) {
    uint32_t a;
    asm("{ .reg .u64 t; cvta.to.shared.u64 t, %1; cvt.u32.u64 %0, t; }" : "=r"(a) : "l"(p));
    return a;
}
__device__ __forceinline__ void ldsm4(uint32_t a, uint32_t& r0, uint32_t& r1,
                                      uint32_t& r2, uint32_t& r3) {
    asm volatile("ldmatrix.sync.aligned.m8n8.x4.shared.b16 {%0,%1,%2,%3}, [%4];"
                 : "=r"(r0), "=r"(r1), "=r"(r2), "=r"(r3) : "r"(a));
}
__device__ __forceinline__ void mma4(float* d, uint32_t a0, uint32_t a1, uint32_t a2,
                                     uint32_t a3, uint32_t b0, uint32_t b1) {
    asm volatile("mma.sync.aligned.m16n8k16.row.col.f32.bf16.bf16.f32 "
                 "{%0,%1,%2,%3},{%4,%5,%6,%7},{%8,%9},{%0,%1,%2,%3};"
                 : "+f"(d[0]), "+f"(d[1]), "+f"(d[2]), "+f"(d[3])
                 : "r"(a0), "r"(a1), "r"(a2), "r"(a3), "r"(b0), "r"(b1));
}
__device__ __forceinline__ void cp16(uint32_t dst, const void* src) {
    asm volatile("cp.async.cg.shared.global [%0], [%1], 16;" :: "r"(dst), "l"(src));
}
#define CP_COMMIT() asm volatile("cp.async.commit_group;" ::: "memory")
#define CP_WAIT1()  asm volatile("cp.async.wait_group 1;" ::: "memory")
#define CP_WAIT0()  asm volatile("cp.async.wait_group 0;" ::: "memory")

// ------------------------------ prep kernels ---------------------------------
__global__ void k_zero() {
    long i = (long)blockIdx.x * blockDim.x + threadIdx.x;
    long nf = 3L * 2 * BB * HH;
    float* pf = &g_h_f32[0][0][0][0];
    for (long j = i; j < nf; j += (long)gridDim.x * blockDim.x) pf[j] = 0.f;
    __nv_bfloat16* pb = &g_hA[0][0][0][0];
    long nb = 3L * 2 * 2 * BB * HH;
    for (long j = i; j < nb; j += (long)gridDim.x * blockDim.x) pb[j] = __float2bfloat16(0.f);
    if (i == 0) { g_bar_count = 0u; g_bar_gen = 0u; }
}

__global__ void k_ig0(const float* __restrict__ emb, const float* __restrict__ w_ih,
                      const float* __restrict__ bias) {
    int idx = blockIdx.x * blockDim.x + threadIdx.x;
    if (idx >= 65 * 1536) return;
    int tok = idx / 1536, j = idx - tok * 1536;
    const float* e = emb + tok * HH;
    const float* w = w_ih + (long)j * HH;
    float acc = bias[j];
    #pragma unroll 8
    for (int k = 0; k < HH; ++k) acc += e[k] * w[k];
    g_ig0[idx] = acc;
}

__global__ void k_prepw(const float* __restrict__ w_ih, const float* __restrict__ w_hh,
                        const float* __restrict__ w_out) {
    long idx = (long)blockIdx.x * 256 + threadIdx.x;     // 6 * 1536 * 512
    if (idx >= 6L * 1536 * 512) return;
    int k = (int)(idx & 511);
    long r = idx >> 9;
    int row = (int)(r % 1536);
    int part = (int)(r / 1536);
    float v = 0.f;
    if (part == 0)      v = w_hh[(long)row * 512 + k];
    else if (part == 1) v = w_ih[(1536L + row) * 512 + k];
    else if (part == 2) v = w_hh[(1536L + row) * 512 + k];
    else if (part == 3) v = w_ih[(2L * 1536 + row) * 512 + k];
    else if (part == 4) v = w_hh[(2L * 1536 + row) * 512 + k];
    else if (row < 65)  v = w_out[(long)row * 512 + k];
    __nv_bfloat16 hi = __float2bfloat16(v);
    __nv_bfloat16 lo = __float2bfloat16(v - __bfloat162float(hi));
    g_wbf[part][0][(long)row * 512 + k] = hi;
    g_wbf[part][1][(long)row * 512 + k] = lo;
}

// ------------------------------ grid barrier ---------------------------------
__device__ __forceinline__ void grid_barrier(unsigned target) {
    __syncthreads();
    if (threadIdx.x == 0) {
        __threadfence();
        unsigned old = atomicAdd(&g_bar_count, 1u);
        if (old == NCTA - 1) {
            g_bar_count = 0u;
            __threadfence();
            atomicAdd(&g_bar_gen, 1u);
        } else {
            while (*((volatile unsigned*)&g_bar_gen) < target) { }
            __threadfence();
        }
    }
    __syncthreads();
}

// ------------------------------ GEMM core ------------------------------------
// Two warpgroups: both consume the SAME staged A chunk (full M=128); each wg
// covers its own W row range (rowbase). Weights persistent in smem, full-K
// pitch (conflict-free: (K+8) elems ≡ 4 words mod 32 banks).
template <int NPH>
__device__ __forceinline__ void gemm_run(
    const __nv_bfloat16* __restrict__ A0h, const __nv_bfloat16* __restrict__ A0l,
    const __nv_bfloat16* __restrict__ A1h, const __nv_bfloat16* __restrict__ A1l,
    uint32_t whi, uint32_t wlo, int pitchB, int rowbase, int ntw,
    uint32_t sb, float (&acc)[NPH][4][4], int tid)
{
    const int warp8 = (tid >> 5) & 7, lane = tid & 31;
    const int lr = lane & 7, gq = lane >> 3;
    const uint32_t aoff = (uint32_t)((warp8 * 16 + lr + (gq & 1) * 8) * 144
                                     + ((gq >> 1) * 8) * 2);
    const int row0 = rowbase + lr + (gq & 1) * 8;

    auto stage = [&](int cg, int buf) {
        int src = cg >> 3, kc = cg & 7;
        const __nv_bfloat16* ah = (src == 0) ? A0h : A1h;
        const __nv_bfloat16* al = (src == 0) ? A0l : A1l;
        uint32_t dst = sb + OFF_A + buf * 2 * APLANE;
        #pragma unroll
        for (int i = 0; i < 4; ++i) {
            int e = tid + i * NTHR;
            int p = e >> 10, rr = (e >> 3) & 127, u = e & 7;
            const __nv_bfloat16* s = (p ? al : ah) + (long)rr * 512 + kc * 64 + u * 8;
            cp16(dst + p * APLANE + rr * 144 + u * 16, s);
        }
        CP_COMMIT();
    };

    stage(0, 0);
    const int TOT = NPH * 8;
    #pragma unroll 1
    for (int cg = 0; cg < TOT; ++cg) {
        const int buf = cg & 1;
        if (cg + 1 < TOT) { stage(cg + 1, buf ^ 1); CP_WAIT1(); }
        else CP_WAIT0();
        __syncthreads();
        const uint32_t ab = sb + OFF_A + buf * 2 * APLANE;
        const int ph = cg >> 3;
        const int kg = ph * 512 + (cg & 7) * 64;
        #pragma unroll
        for (int ks = 0; ks < 4; ++ks) {
            uint32_t Ah0, Ah1, Ah2, Ah3, Al0, Al1, Al2, Al3;
            ldsm4(ab + aoff + ks * 32, Ah0, Ah1, Ah2, Ah3);
            ldsm4(ab + APLANE + aoff + ks * 32, Al0, Al1, Al2, Al3);
            const uint32_t kbyte = (uint32_t)(kg + ks * 16 + (gq >> 1) * 8) * 2;
            #pragma unroll
            for (int p = 0; p < 2; ++p) {
                if (2 * p < ntw) {
                    uint32_t wo = (uint32_t)(row0 + p * 16) * (uint32_t)pitchB + kbyte;
                    uint32_t Bh0, Bh1, Bh2, Bh3, Bl0, Bl1, Bl2, Bl3;
                    ldsm4(whi + wo, Bh0, Bh1, Bh2, Bh3);
                    ldsm4(wlo + wo, Bl0, Bl1, Bl2, Bl3);
                    float* d0 = acc[ph][2 * p];
                    mma4(d0, Ah0, Ah1, Ah2, Ah3, Bh0, Bh2);
                    mma4(d0, Ah0, Ah1, Ah2, Ah3, Bl0, Bl2);
                    mma4(d0, Al0, Al1, Al2, Al3, Bh0, Bh2);
                    if (2 * p + 1 < ntw) {
                        float* d1 = acc[ph][2 * p + 1];
                        mma4(d1, Ah0, Ah1, Ah2, Ah3, Bh1, Bh3);
                        mma4(d1, Ah0, Ah1, Ah2, Ah3, Bl1, Bl3);
                        mma4(d1, Al0, Al1, Al2, Al3, Bh1, Bh3);
                    }
                }
            }
        }
        __syncthreads();
    }
}

__device__ __forceinline__ void write_gates(float* __restrict__ gbuf,
                                            const float (*acc)[4],
                                            int n0w, int ntw, int tid)
{
    const int warp8 = (tid >> 5) & 7, lane = tid & 31;
    const int nb = n0w + (lane & 3) * 2;
    const int b0 = warp8 * 16 + (lane >> 2);
    #pragma unroll
    for (int j = 0; j < 4; ++j) {
        if (j < ntw) {
            int n = nb + j * 8;
            *(float2*)(gbuf + (long)b0 * 1536 + n)       = make_float2(acc[j][0], acc[j][1]);
            *(float2*)(gbuf + (long)(b0 + 8) * 1536 + n) = make_float2(acc[j][2], acc[j][3]);
        }
    }
}

// ------------------------------- main kernel ---------------------------------
__global__ void __launch_bounds__(NTHR, 1) k_main(
    const int* __restrict__ x_seq,
    const float* __restrict__ bias, const float* __restrict__ b_n,
    const float* __restrict__ b_out, float* __restrict__ out)
{
    extern __shared__ unsigned char smem[];
    const uint32_t sb = smem_u32(smem);
    const int tid = threadIdx.x;
    const int wg = tid >> 8;
    const int cta = blockIdx.x;

    // ---- role decode ----
    int role, lay = 0, n0 = 0, rows_alloc, ntw, rowbase, ktot, p0, p1;
    if (cta < 24) {
        role = 0; lay = 0; n0 = cta * 64; rows_alloc = 64;
        ntw = 4; rowbase = wg * 32; ktot = 512; p0 = 0; p1 = 0;
    } else if (cta < 72) {
        role = 1; lay = 1; n0 = (cta - 24) * 32; rows_alloc = 32;
        ntw = 2; rowbase = wg * 16; ktot = 1024; p0 = 1; p1 = 2;
    } else if (cta < 120) {
        role = 2; lay = 2; n0 = (cta - 72) * 32; rows_alloc = 32;
        ntw = 2; rowbase = wg * 16; ktot = 1024; p0 = 3; p1 = 4;
    } else {
        role = 3; lay = 3; n0 = (cta - 120) * 40; rows_alloc = 48;
        ntw = wg ? 2 : 3; rowbase = wg * 24; ktot = 512; p0 = 5; p1 = 5;
    }
    const int wpitch_e = ktot + 8;               // elements
    const int pitchB = wpitch_e * 2;             // bytes
    const int wplane = rows_alloc * pitchB;      // bytes
    const uint32_t whi = sb + OFF_W, wlo = whi + (uint32_t)wplane;

    // ---- persistent weight load ----
    {
        __nv_bfloat16* whs = (__nv_bfloat16*)(smem + OFF_W);
        __nv_bfloat16* wls = (__nv_bfloat16*)(smem + OFF_W + wplane);
        for (int e = tid; e < rows_alloc * ktot; e += NTHR) {
            int r = e / ktot, k = e - r * ktot;
            int grow = n0 + r; if (grow > 1535) grow = 0;
            int part = (k < 512) ? p0 : p1;
            int kk = k & 511;
            whs[r * wpitch_e + k] = g_wbf[part][0][(long)grow * 512 + kk];
            wls[r * wpitch_e + k] = g_wbf[part][1][(long)grow * 512 + kk];
        }
    }
    __syncthreads();

    const int gtid = cta * NTHR + tid;
    const int lane = tid & 31, warp8 = (tid >> 5) & 7;

    for (int s = 0; s < TT + 3; ++s) {
        const int rd = (s + 1) & 1, wr = s & 1;

        // ================= phase 1: GEMMs =====================================
        bool active;
        if (role == 0)      active = (s < TT);
        else if (role == 1) active = (s >= 1 && s <= TT);
        else if (role == 2) active = (s >= 2 && s <= TT + 1);
        else                active = (s >= 3);

        if (active) {
            if (role == 0) {
                float acc[1][4][4] = {};
                gemm_run<1>(g_hA[0][rd][0], g_hA[0][rd][1], g_hA[0][rd][0], g_hA[0][rd][1],
                            whi, wlo, pitchB, rowbase, ntw, sb, acc, tid);
                write_gates(&g_gh[0][0][0], acc[0], n0 + rowbase, ntw, tid);
            } else if (role == 3) {
                float acc[1][4][4] = {};
                gemm_run<1>(g_hA[2][rd][0], g_hA[2][rd][1], g_hA[2][rd][0], g_hA[2][rd][1],
                            whi, wlo, pitchB, rowbase, ntw, sb, acc, tid);
                const int t = s - 3;
                const int nb = n0 + rowbase + (lane & 3) * 2;
                const int b0 = warp8 * 16 + (lane >> 2);
                #pragma unroll
                for (int j = 0; j < 3; ++j) {
                    if (j < ntw) {
                        int n = nb + j * 8;
                        #pragma unroll
                        for (int dn = 0; dn < 2; ++dn) {
                            int v = n + dn;
                            if (v < 65) {
                                float bo = __ldg(b_out + v);
                                out[((long)b0 * TT + t) * 65 + v]       = acc[0][j][dn]     + bo;
                                out[((long)(b0 + 8) * TT + t) * 65 + v] = acc[0][j][2 + dn] + bo;
                            }
                        }
                    }
                }
            } else {
                float acc[2][4][4] = {};
                gemm_run<2>(g_hA[lay - 1][rd][0], g_hA[lay - 1][rd][1],
                            g_hA[lay][rd][0], g_hA[lay][rd][1],
                            whi, wlo, pitchB, rowbase, ntw, sb, acc, tid);
                write_gates(&g_gi[lay - 1][0][0], acc[0], n0 + rowbase, ntw, tid);
                write_gates(&g_gh[lay][0][0],     acc[1], n0 + rowbase, ntw, tid);
            }
        }

        grid_barrier((unsigned)(2 * s + 1));

        // ================= phase 2: GRU nonlinearity -> h slabs ==============
        if (s < TT) {                       // layer 0, t = s
            const int t = s;
            for (int e = gtid; e < BB * HH; e += GT) {
                int b = e >> 9, g = e & 511;
                int tok = __ldg(x_seq + (long)b * TT + t);
                const float* ig = g_ig0 + (long)tok * 1536;
                const float* gh = &g_gh[0][0][0] + (long)b * 1536;
                float hr = __ldcv(gh + g);
                float hz = __ldcv(gh + 512 + g);
                float hn = __ldcv(gh + 1024 + g);
                float r = sigm(ig[g] + hr);
                float z = sigm(ig[512 + g] + hz);
                float n = tanhf(ig[1024 + g] + r * (hn + b_n[g]));
                float hp = g_h_f32[0][rd][b][g];
                float h = n + z * (hp - n);
                g_h_f32[0][wr][b][g] = h;
                __nv_bfloat16 hi = __float2bfloat16(h);
                __nv_bfloat16 lo = __float2bfloat16(h - __bfloat162float(hi));
                g_hA[0][wr][0][e] = hi;
                g_hA[0][wr][1][e] = lo;
            }
        }
        #pragma unroll
        for (int ly = 1; ly <= 2; ++ly) {
            if (s >= ly && s <= TT + ly - 1) {
                const float* bl = bias + (long)ly * 1536;
                const float* bnl = b_n + (long)ly * 512;
                const float* gib = &g_gi[ly - 1][0][0];
                const float* ghb = &g_gh[ly][0][0];
                for (int e = gtid; e < BB * HH; e += GT) {
                    int b = e >> 9, g = e & 511;
                    const float* gi = gib + (long)b * 1536;
                    const float* gh = ghb + (long)b * 1536;
                    float ir = __ldcv(gi + g)        + bl[g];
                    float iz = __ldcv(gi + 512 + g)  + bl[512 + g];
                    float in_ = __ldcv(gi + 1024 + g) + bl[1024 + g];
                    float hr = __ldcv(gh + g);
                    float hz = __ldcv(gh + 512 + g);
                    float hn = __ldcv(gh + 1024 + g);
                    float r = sigm(ir + hr);
                    float z = sigm(iz + hz);
                    float n = tanhf(in_ + r * (hn + bnl[g]));
                    float hp = g_h_f32[ly][rd][b][g];
                    float h = n + z * (hp - n);
                    g_h_f32[ly][wr][b][g] = h;
                    __nv_bfloat16 hi = __float2bfloat16(h);
                    __nv_bfloat16 lo = __float2bfloat16(h - __bfloat162float(hi));
                    g_hA[ly][wr][0][e] = hi;
                    g_hA[ly][wr][1][e] = lo;
                }
            }
        }

        grid_barrier((unsigned)(2 * s + 2));
    }
}

// --------------------------------- launch ------------------------------------
extern "C" void kernel_launch(void* const* d_in, const int* in_sizes, int n_in,
                              void* d_out, int out_size) {
    const int*   x_seq = (const int*)  d_in[0];
    const float* emb   = (const float*)d_in[1];
    const float* w_ih  = (const float*)d_in[2];
    const float* w_hh  = (const float*)d_in[3];
    const float* b     = (const float*)d_in[4];
    const float* b_n   = (const float*)d_in[5];
    const float* w_out = (const float*)d_in[6];
    const float* b_out = (const float*)d_in[7];
    float* out = (float*)d_out;

    cudaFuncSetAttribute(k_main, cudaFuncAttributeMaxDynamicSharedMemorySize, SMEM_BYTES);

    k_zero<<<512, 256>>>();
    k_ig0<<<(65 * 1536 + 255) / 256, 256>>>(emb, w_ih, b);
    k_prepw<<<(int)((6L * 1536 * 512 + 255) / 256), 256>>>(w_ih, w_hh, w_out);
    k_main<<<NCTA, NTHR, SMEM_BYTES>>>(x_seq, b, b_n, b_out, out);
}